// round 3
// baseline (speedup 1.0000x reference)
#include <cuda_runtime.h>
#include <math.h>
#include <stdint.h>

#define LVOX 4096
#define NBATCH 4
#define NB 8          // (branch, batch) pairs
#define MAXN 32       // max neighbors per voxel (analytic bound: <= 27)
#define CPB 10        // channels per phase-B block  (320/10 = 32 blocks per batch)
#define TPB_A 512
#define TPB_B 512

// Scratch: static device globals (no allocation allowed)
__device__ int            g_ncnt[NB][LVOX];
__device__ unsigned short g_nbr[NB][MAXN][LVOX];   // t-major: coalesced over l
__device__ unsigned int   g_total[NB];
__device__ double         g_num[NB];
__device__ unsigned int   g_done;

// ───────────────────────── Phase A ─────────────────────────
// One block per nb = (branch, batch). Computes neighbor lists, block-reduced
// pair count (no global atomics), and resets this nb's accumulators.
__global__ void k_phaseA(const float* __restrict__ cq, const float* __restrict__ ck) {
    int nb  = blockIdx.x;
    int tid = threadIdx.x;
    int br = nb >> 2;
    int n  = nb & 3;
    int qb = br ? (3 - n) : n;     // flipped q-batch for branch 1

    if (tid == 0) {
        g_num[nb] = 0.0;
        if (nb == 0) g_done = 0u;
    }

    // q crop box (batch qb — flipped for branch 1)
    float q0 = cq[qb*6+0], q1 = cq[qb*6+1], q2 = cq[qb*6+2];
    float bq0 = (cq[qb*6+3] - q0) * (1.0f/16.0f);
    float bq1 = (cq[qb*6+4] - q1) * (1.0f/16.0f);
    float bq2 = (cq[qb*6+5] - q2) * (1.0f/16.0f);
    // k crop box (batch n)
    float k0 = ck[n*6+0], k1 = ck[n*6+1], k2 = ck[n*6+2];
    float bk0 = (ck[n*6+3] - k0) * (1.0f/16.0f);
    float bk1 = (ck[n*6+4] - k1) * (1.0f/16.0f);
    float bk2 = (ck[n*6+5] - k2) * (1.0f/16.0f);

    // max_diag uses UNFLIPPED diag_q[n], diag_k[n]
    float a0 = (cq[n*6+3] - cq[n*6+0]) * (1.0f/16.0f);
    float a1 = (cq[n*6+4] - cq[n*6+1]) * (1.0f/16.0f);
    float a2 = (cq[n*6+5] - cq[n*6+2]) * (1.0f/16.0f);
    float diagq = sqrtf((a0*a0 + a1*a1) + a2*a2);
    float diagk = sqrtf((bk0*bk0 + bk1*bk1) + bk2*bk2);
    float md = fmaxf(diagq, diagk);
    float R  = 0.5f * md;

    int mycount = 0;
    for (int l = tid; l < LVOX; l += TPB_A) {
        int i  = l >> 8;
        int j  = (l >> 4) & 15;
        int kz = l & 15;
        float cx = fmaf((float)i  + 0.5f, bq0, q0);
        float cy = fmaf((float)j  + 0.5f, bq1, q1);
        float cz = fmaf((float)kz + 0.5f, bq2, q2);

        int xlo = max(0,  (int)floorf((cx - R - k0) / bk0 - 0.5f));
        int xhi = min(15, (int)ceilf ((cx + R - k0) / bk0 - 0.5f));
        int ylo = max(0,  (int)floorf((cy - R - k1) / bk1 - 0.5f));
        int yhi = min(15, (int)ceilf ((cy + R - k1) / bk1 - 0.5f));
        int zlo = max(0,  (int)floorf((cz - R - k2) / bk2 - 0.5f));
        int zhi = min(15, (int)ceilf ((cz + R - k2) / bk2 - 0.5f));

        int cnt = 0;
        for (int jx = xlo; jx <= xhi; jx++) {
            float dx = cx - fmaf((float)jx + 0.5f, bk0, k0);
            for (int jy = ylo; jy <= yhi; jy++) {
                float dy = cy - fmaf((float)jy + 0.5f, bk1, k1);
                for (int jz = zlo; jz <= zhi; jz++) {
                    float dz = cz - fmaf((float)jz + 0.5f, bk2, k2);
                    float d2 = dx*dx + dy*dy + dz*dz;
                    // Exact reference semantics: sqrt then divide then compare
                    if (sqrtf(d2) / md < 0.5f) {
                        if (cnt < MAXN)
                            g_nbr[nb][cnt][l] = (unsigned short)(jx*256 + jy*16 + jz);
                        cnt++;
                    }
                }
            }
        }
        if (cnt > MAXN) cnt = MAXN;
        g_ncnt[nb][l] = cnt;
        mycount += cnt;
    }

    // Block-reduce count (no global atomics)
    __shared__ int red[TPB_A / 32];
    for (int o = 16; o; o >>= 1) mycount += __shfl_down_sync(0xFFFFFFFFu, mycount, o);
    if ((tid & 31) == 0) red[tid >> 5] = mycount;
    __syncthreads();
    if (tid == 0) {
        int s = 0;
        for (int w = 0; w < TPB_A / 32; w++) s += red[w];
        g_total[nb] = (unsigned int)s;
    }
}

// ───────────────────────── Phase B (+ fused finalize) ─────────────────────────
// Block = (batch n, chunk of CPB channels). Stages ONLY k[n] channels in smem;
// q is read streaming from gmem. Handles BOTH branches for n.
__global__ void k_phaseB(const float* __restrict__ q, const float* __restrict__ k,
                         float* __restrict__ out, int nblocks) {
    int n      = blockIdx.y;   // 0..3
    int cchunk = blockIdx.x;   // 0..31
    int c0     = cchunk * CPB;
    extern __shared__ float kk[];   // [CPB][LVOX]
    int tid = threadIdx.x;
    int qb2 = 3 - n;

    // Stage k channels
    for (int cc = 0; cc < CPB; cc++) {
        const float* kr = k + ((size_t)n * 320 + (c0 + cc)) * (size_t)LVOX;
        float* dst = kk + (size_t)cc * LVOX;
        for (int i = tid; i < LVOX; i += TPB_B) dst[i] = kr[i];
    }
    __syncthreads();

    int nb0 = n, nb1 = 4 + n;
    const float* qn = q + ((size_t)n   * 320 + c0) * (size_t)LVOX;
    const float* qf = q + ((size_t)qb2 * 320 + c0) * (size_t)LVOX;

    float acc0[CPB], acc1[CPB];
#pragma unroll
    for (int cc = 0; cc < CPB; cc++) { acc0[cc] = 0.f; acc1[cc] = 0.f; }

    for (int l = tid; l < LVOX; l += TPB_B) {
        int cnt0 = g_ncnt[nb0][l];
        if (cnt0) {
            float s[CPB];
#pragma unroll
            for (int cc = 0; cc < CPB; cc++) s[cc] = 0.f;
            for (int t = 0; t < cnt0; t++) {
                int m = g_nbr[nb0][t][l];
#pragma unroll
                for (int cc = 0; cc < CPB; cc++) s[cc] += kk[cc * LVOX + m];
            }
#pragma unroll
            for (int cc = 0; cc < CPB; cc++)
                acc0[cc] = fmaf(qn[(size_t)cc * LVOX + l], s[cc], acc0[cc]);
        }
        int cnt1 = g_ncnt[nb1][l];
        if (cnt1) {
            float s[CPB];
#pragma unroll
            for (int cc = 0; cc < CPB; cc++) s[cc] = 0.f;
            for (int t = 0; t < cnt1; t++) {
                int m = g_nbr[nb1][t][l];
#pragma unroll
                for (int cc = 0; cc < CPB; cc++) s[cc] += kk[cc * LVOX + m];
            }
#pragma unroll
            for (int cc = 0; cc < CPB; cc++)
                acc1[cc] = fmaf(qf[(size_t)cc * LVOX + l], s[cc], acc1[cc]);
        }
    }

    double t0 = 0.0, t1 = 0.0;
#pragma unroll
    for (int cc = 0; cc < CPB; cc++) { t0 += (double)acc0[cc]; t1 += (double)acc1[cc]; }
    for (int o = 16; o; o >>= 1) {
        t0 += __shfl_down_sync(0xFFFFFFFFu, t0, o);
        t1 += __shfl_down_sync(0xFFFFFFFFu, t1, o);
    }
    __shared__ double red0[TPB_B / 32], red1[TPB_B / 32];
    if ((tid & 31) == 0) { red0[tid >> 5] = t0; red1[tid >> 5] = t1; }
    __syncthreads();
    if (tid == 0) {
        double s0 = 0.0, s1 = 0.0;
        for (int w = 0; w < TPB_B / 32; w++) { s0 += red0[w]; s1 += red1[w]; }
        atomicAdd(&g_num[nb0], s0);
        atomicAdd(&g_num[nb1], s1);
        __threadfence();
        unsigned int ticket = atomicAdd(&g_done, 1u);
        if (ticket == (unsigned int)(nblocks - 1)) {
            // Last block to finish finalizes the scalar (all prior g_num adds
            // are visible: each contributor fenced before its ticket add).
            double a = 0.0, b = 0.0;
            for (int m = 0; m < NBATCH; m++) {
                a += g_num[m]     / ((double)g_total[m]     + 1e-6);
                b += g_num[4 + m] / ((double)g_total[4 + m] + 1e-6);
            }
            out[0] = (float)(-2.0 * (a / 4.0) - 2.0 * (b / 4.0));
        }
    }
}

extern "C" void kernel_launch(void* const* d_in, const int* in_sizes, int n_in,
                              void* d_out, int out_size) {
    const float* q  = (const float*)d_in[0];
    const float* k  = (const float*)d_in[1];
    const float* cq = (const float*)d_in[2];
    const float* ck = (const float*)d_in[3];

    // 160KB dynamic smem opt-in (idempotent; legal during capture)
    (void)cudaFuncSetAttribute(k_phaseB, cudaFuncAttributeMaxDynamicSharedMemorySize,
                               CPB * LVOX * (int)sizeof(float));

    k_phaseA<<<NB, TPB_A>>>(cq, ck);
    dim3 gb(320 / CPB, NBATCH);
    k_phaseB<<<gb, TPB_B, CPB * LVOX * (int)sizeof(float)>>>(q, k, (float*)d_out,
                                                             (320 / CPB) * NBATCH);
}

// round 4
// speedup vs baseline: 2.2413x; 2.2413x over previous
#include <cuda_runtime.h>
#include <math.h>
#include <stdint.h>

#define LVOX 4096
#define NBATCH 4
#define NB 8          // (branch, batch) pairs
#define MAXN 32       // max neighbors per voxel (analytic bound: <= 27)
#define CPB 4         // channels per phase-B block (64KB smem -> 3 CTAs/SM)
#define TPB_A 256
#define ABLK 16       // phase-A blocks per nb
#define TPB_B 512

// Scratch: static device globals (no allocation allowed)
__device__ int            g_ncnt[NB][LVOX];
__device__ unsigned short g_nbr[NB][MAXN][LVOX];   // t-major: coalesced over l
__device__ int            g_partial[NB][ABLK];     // per-block pair counts
__device__ double         g_num[NB];
__device__ unsigned int   g_done;

// ───────────────────────── Phase A ─────────────────────────
// Grid (ABLK, NB), 256 threads: one thread per (nb, l). Partial counts are
// block-reduced into g_partial (no atomics, no pre-zero needed).
__global__ void k_phaseA(const float* __restrict__ cq, const float* __restrict__ ck) {
    int nb  = blockIdx.y;
    int l   = blockIdx.x * TPB_A + threadIdx.x;
    int tid = threadIdx.x;
    int br = nb >> 2;
    int n  = nb & 3;
    int qb = br ? (3 - n) : n;     // flipped q-batch for branch 1

    if (blockIdx.x == 0 && tid == 0) {
        g_num[nb] = 0.0;           // consumed only by phase B (after kernel boundary)
        if (nb == 0) g_done = 0u;
    }

    // q crop box (batch qb — flipped for branch 1)
    float q0 = cq[qb*6+0], q1 = cq[qb*6+1], q2 = cq[qb*6+2];
    float bq0 = (cq[qb*6+3] - q0) * (1.0f/16.0f);
    float bq1 = (cq[qb*6+4] - q1) * (1.0f/16.0f);
    float bq2 = (cq[qb*6+5] - q2) * (1.0f/16.0f);
    // k crop box (batch n)
    float k0 = ck[n*6+0], k1 = ck[n*6+1], k2 = ck[n*6+2];
    float bk0 = (ck[n*6+3] - k0) * (1.0f/16.0f);
    float bk1 = (ck[n*6+4] - k1) * (1.0f/16.0f);
    float bk2 = (ck[n*6+5] - k2) * (1.0f/16.0f);

    // max_diag uses UNFLIPPED diag_q[n], diag_k[n]
    float a0 = (cq[n*6+3] - cq[n*6+0]) * (1.0f/16.0f);
    float a1 = (cq[n*6+4] - cq[n*6+1]) * (1.0f/16.0f);
    float a2 = (cq[n*6+5] - cq[n*6+2]) * (1.0f/16.0f);
    float diagq = sqrtf((a0*a0 + a1*a1) + a2*a2);
    float diagk = sqrtf((bk0*bk0 + bk1*bk1) + bk2*bk2);
    float md = fmaxf(diagq, diagk);
    float R  = 0.5f * md;

    int i  = l >> 8;
    int j  = (l >> 4) & 15;
    int kz = l & 15;
    float cx = fmaf((float)i  + 0.5f, bq0, q0);
    float cy = fmaf((float)j  + 0.5f, bq1, q1);
    float cz = fmaf((float)kz + 0.5f, bq2, q2);

    int xlo = max(0,  (int)floorf((cx - R - k0) / bk0 - 0.5f));
    int xhi = min(15, (int)ceilf ((cx + R - k0) / bk0 - 0.5f));
    int ylo = max(0,  (int)floorf((cy - R - k1) / bk1 - 0.5f));
    int yhi = min(15, (int)ceilf ((cy + R - k1) / bk1 - 0.5f));
    int zlo = max(0,  (int)floorf((cz - R - k2) / bk2 - 0.5f));
    int zhi = min(15, (int)ceilf ((cz + R - k2) / bk2 - 0.5f));

    int cnt = 0;
    for (int jx = xlo; jx <= xhi; jx++) {
        float dx = cx - fmaf((float)jx + 0.5f, bk0, k0);
        for (int jy = ylo; jy <= yhi; jy++) {
            float dy = cy - fmaf((float)jy + 0.5f, bk1, k1);
            for (int jz = zlo; jz <= zhi; jz++) {
                float dz = cz - fmaf((float)jz + 0.5f, bk2, k2);
                float d2 = dx*dx + dy*dy + dz*dz;
                // Exact reference semantics: sqrt then divide then compare
                if (sqrtf(d2) / md < 0.5f) {
                    if (cnt < MAXN)
                        g_nbr[nb][cnt][l] = (unsigned short)(jx*256 + jy*16 + jz);
                    cnt++;
                }
            }
        }
    }
    if (cnt > MAXN) cnt = MAXN;
    g_ncnt[nb][l] = cnt;

    // Block-reduce pair count into g_partial
    __shared__ int red[TPB_A / 32];
    int mc = cnt;
    for (int o = 16; o; o >>= 1) mc += __shfl_down_sync(0xFFFFFFFFu, mc, o);
    if ((tid & 31) == 0) red[tid >> 5] = mc;
    __syncthreads();
    if (tid == 0) {
        int s = 0;
        for (int w = 0; w < TPB_A / 32; w++) s += red[w];
        g_partial[nb][blockIdx.x] = s;
    }
}

// ───────────────────────── Phase B (+ fused finalize) ─────────────────────────
// Block = (batch n, chunk of CPB channels). Stages ONLY k[n] channels in smem;
// q is read streaming from gmem. Handles BOTH branches for n.
__global__ void __launch_bounds__(TPB_B, 3)
k_phaseB(const float* __restrict__ q, const float* __restrict__ k,
         float* __restrict__ out, int nblocks) {
    int n      = blockIdx.y;   // 0..3
    int cchunk = blockIdx.x;   // 0..79
    int c0     = cchunk * CPB;
    extern __shared__ float kk[];   // [CPB][LVOX]  = 64KB
    int tid = threadIdx.x;
    int qb2 = 3 - n;

    // Stage k channels (vectorized)
#pragma unroll
    for (int cc = 0; cc < CPB; cc++) {
        const float4* kr = (const float4*)(k + ((size_t)n * 320 + (c0 + cc)) * (size_t)LVOX);
        float4* dst = (float4*)(kk + (size_t)cc * LVOX);
        for (int i = tid; i < LVOX / 4; i += TPB_B) dst[i] = kr[i];
    }
    __syncthreads();

    int nb0 = n, nb1 = 4 + n;
    const float* qn = q + ((size_t)n   * 320 + c0) * (size_t)LVOX;
    const float* qf = q + ((size_t)qb2 * 320 + c0) * (size_t)LVOX;

    float acc0[CPB], acc1[CPB];
#pragma unroll
    for (int cc = 0; cc < CPB; cc++) { acc0[cc] = 0.f; acc1[cc] = 0.f; }

    for (int l = tid; l < LVOX; l += TPB_B) {
        int cnt0 = g_ncnt[nb0][l];
        if (cnt0) {
            float s[CPB];
#pragma unroll
            for (int cc = 0; cc < CPB; cc++) s[cc] = 0.f;
            for (int t = 0; t < cnt0; t++) {
                int m = g_nbr[nb0][t][l];
#pragma unroll
                for (int cc = 0; cc < CPB; cc++) s[cc] += kk[cc * LVOX + m];
            }
#pragma unroll
            for (int cc = 0; cc < CPB; cc++)
                acc0[cc] = fmaf(qn[(size_t)cc * LVOX + l], s[cc], acc0[cc]);
        }
        int cnt1 = g_ncnt[nb1][l];
        if (cnt1) {
            float s[CPB];
#pragma unroll
            for (int cc = 0; cc < CPB; cc++) s[cc] = 0.f;
            for (int t = 0; t < cnt1; t++) {
                int m = g_nbr[nb1][t][l];
#pragma unroll
                for (int cc = 0; cc < CPB; cc++) s[cc] += kk[cc * LVOX + m];
            }
#pragma unroll
            for (int cc = 0; cc < CPB; cc++)
                acc1[cc] = fmaf(qf[(size_t)cc * LVOX + l], s[cc], acc1[cc]);
        }
    }

    double t0 = 0.0, t1 = 0.0;
#pragma unroll
    for (int cc = 0; cc < CPB; cc++) { t0 += (double)acc0[cc]; t1 += (double)acc1[cc]; }
    for (int o = 16; o; o >>= 1) {
        t0 += __shfl_down_sync(0xFFFFFFFFu, t0, o);
        t1 += __shfl_down_sync(0xFFFFFFFFu, t1, o);
    }
    __shared__ double red0[TPB_B / 32], red1[TPB_B / 32];
    if ((tid & 31) == 0) { red0[tid >> 5] = t0; red1[tid >> 5] = t1; }
    __syncthreads();
    if (tid == 0) {
        double s0 = 0.0, s1 = 0.0;
        for (int w = 0; w < TPB_B / 32; w++) { s0 += red0[w]; s1 += red1[w]; }
        atomicAdd(&g_num[nb0], s0);
        atomicAdd(&g_num[nb1], s1);
        __threadfence();
        unsigned int ticket = atomicAdd(&g_done, 1u);
        if (ticket == (unsigned int)(nblocks - 1)) {
            // Last block finalizes: all prior g_num adds visible (each
            // contributor fenced before its ticket add).
            double a = 0.0, b = 0.0;
            for (int m = 0; m < NBATCH; m++) {
                int tot0 = 0, tot1 = 0;
                for (int w = 0; w < ABLK; w++) {
                    tot0 += g_partial[m][w];
                    tot1 += g_partial[4 + m][w];
                }
                a += g_num[m]     / ((double)tot0 + 1e-6);
                b += g_num[4 + m] / ((double)tot1 + 1e-6);
            }
            out[0] = (float)(-2.0 * (a / 4.0) - 2.0 * (b / 4.0));
        }
    }
}

extern "C" void kernel_launch(void* const* d_in, const int* in_sizes, int n_in,
                              void* d_out, int out_size) {
    const float* q  = (const float*)d_in[0];
    const float* k  = (const float*)d_in[1];
    const float* cq = (const float*)d_in[2];
    const float* ck = (const float*)d_in[3];

    (void)cudaFuncSetAttribute(k_phaseB, cudaFuncAttributeMaxDynamicSharedMemorySize,
                               CPB * LVOX * (int)sizeof(float));

    dim3 ga(ABLK, NB);
    k_phaseA<<<ga, TPB_A>>>(cq, ck);
    dim3 gb(320 / CPB, NBATCH);
    k_phaseB<<<gb, TPB_B, CPB * LVOX * (int)sizeof(float)>>>(q, k, (float*)d_out,
                                                             (320 / CPB) * NBATCH);
}